// round 2
// baseline (speedup 1.0000x reference)
#include <cuda_runtime.h>
#include <cuda_bf16.h>
#include <math.h>
#include <stdint.h>

// Problem shapes (fixed for this problem instance)
#define NB  256   // batch N
#define NT  512   // Nt
#define NX  512   // Nx

// ---------------------------------------------------------------------------
// Device scratch (no allocations allowed)
// ---------------------------------------------------------------------------
__device__ int    g_T0[NB];
__device__ double g_Wd[NX * NX];     // fp64 working copy of W for LU
__device__ double g_logabsdet;

// ---------------------------------------------------------------------------
// Kernel 1: per-sample T0 = min(argmin_t |phi[b,t,0]|, argmin_t |phi[b,t,1]|)
// argmin semantics: first occurrence of the minimum (strict < keeps first).
// One warp per sample.
// ---------------------------------------------------------------------------
__global__ void argmin_kernel(const float* __restrict__ phi) {
    int b = blockIdx.x;
    int lane = threadIdx.x;
    const float* p = phi + (size_t)b * NT * NX;

    float bv0 = 1e38f; int bi0 = 0;
    float bv1 = 1e38f; int bi1 = 0;
    for (int t = lane; t < NT; t += 32) {
        float v0 = fabsf(p[(size_t)t * NX + 0]);
        float v1 = fabsf(p[(size_t)t * NX + 1]);
        if (v0 < bv0) { bv0 = v0; bi0 = t; }
        if (v1 < bv1) { bv1 = v1; bi1 = t; }
    }
    #pragma unroll
    for (int o = 16; o; o >>= 1) {
        float ov = __shfl_down_sync(0xffffffffu, bv0, o);
        int   oi = __shfl_down_sync(0xffffffffu, bi0, o);
        if (ov < bv0 || (ov == bv0 && oi < bi0)) { bv0 = ov; bi0 = oi; }
        ov = __shfl_down_sync(0xffffffffu, bv1, o);
        oi = __shfl_down_sync(0xffffffffu, bi1, o);
        if (ov < bv1 || (ov == bv1 && oi < bi1)) { bv1 = ov; bi1 = oi; }
    }
    if (lane == 0) {
        g_T0[b] = (bi0 > bi1) ? bi1 : bi0;
    }
}

// ---------------------------------------------------------------------------
// Kernel 2: W (fp32) -> g_Wd (fp64), reset logdet accumulator
// ---------------------------------------------------------------------------
__global__ void convert_W_kernel(const float* __restrict__ W) {
    int i = blockIdx.x * blockDim.x + threadIdx.x;
    if (i < NX * NX) g_Wd[i] = (double)W[i];
    if (i == 0) g_logabsdet = 0.0;
}

// ---------------------------------------------------------------------------
// LU (fp64, partial pivoting, blocked nb=32). Only |pivot| products needed.
// ---------------------------------------------------------------------------
#define LU_NB 32

// Panel factorization: single block, panel held in shared memory.
// Also applies row swaps to the trailing columns [k0+32, 512) (LASWP),
// and accumulates sum(log|pivot|).
__global__ void lu_panel_kernel(int k0) {
    extern __shared__ double P[];           // R rows x 33 (padded)
    __shared__ double s_redv[16];
    __shared__ int    s_redi[16];
    __shared__ int    s_pivrow;
    __shared__ double s_pivinv;
    __shared__ double s_logsum;
    __shared__ int    s_piv[LU_NB];

    const int R = NX - k0;                  // active rows
    const int tid = threadIdx.x;            // 512 threads

    // Load panel into smem
    for (int i = tid; i < R * LU_NB; i += 512) {
        int r = i >> 5, c = i & 31;
        P[r * 33 + c] = g_Wd[(size_t)(k0 + r) * NX + k0 + c];
    }
    if (tid == 0) s_logsum = 0.0;
    __syncthreads();

    for (int j = 0; j < LU_NB; j++) {
        // --- pivot search over local rows r in [j, R) ---
        double v = -1.0; int idx = j;
        int r = j + tid;
        if (r < R) { v = fabs(P[r * 33 + j]); idx = r; }
        #pragma unroll
        for (int o = 16; o; o >>= 1) {
            double ov = __shfl_down_sync(0xffffffffu, v, o);
            int    oi = __shfl_down_sync(0xffffffffu, idx, o);
            if (ov > v) { v = ov; idx = oi; }
        }
        if ((tid & 31) == 0) { s_redv[tid >> 5] = v; s_redi[tid >> 5] = idx; }
        __syncthreads();
        if (tid == 0) {
            double bv = s_redv[0]; int bi = s_redi[0];
            for (int q = 1; q < 16; q++)
                if (s_redv[q] > bv) { bv = s_redv[q]; bi = s_redi[q]; }
            s_pivrow = bi; s_piv[j] = bi;
        }
        __syncthreads();
        int pr = s_pivrow;
        if (pr != j) {
            if (tid < LU_NB) {
                double t1 = P[j * 33 + tid];
                P[j * 33 + tid] = P[pr * 33 + tid];
                P[pr * 33 + tid] = t1;
            }
            __syncthreads();
        }
        if (tid == 0) {
            double pv = P[j * 33 + j];
            s_logsum += log(fabs(pv));
            s_pivinv = 1.0 / pv;
        }
        __syncthreads();
        double pinv = s_pivinv;
        // --- scale + rank-1 update of remaining panel columns ---
        r = j + 1 + tid;
        if (r < R) {
            double m = P[r * 33 + j] * pinv;
            P[r * 33 + j] = m;
            for (int c = j + 1; c < LU_NB; c++)
                P[r * 33 + c] -= m * P[j * 33 + c];
        }
        __syncthreads();
    }

    // Write back panel
    for (int i = tid; i < R * LU_NB; i += 512) {
        int r = i >> 5, c = i & 31;
        g_Wd[(size_t)(k0 + r) * NX + k0 + c] = P[r * 33 + c];
    }
    __syncthreads();

    // Apply recorded row swaps to trailing columns (columns < k0 never read again)
    int trail = NX - k0 - LU_NB;
    for (int j = 0; j < LU_NB; j++) {
        int pr = s_piv[j];
        if (pr != j) {
            for (int c = tid; c < trail; c += 512) {
                size_t a1 = (size_t)(k0 + j)  * NX + k0 + LU_NB + c;
                size_t a2 = (size_t)(k0 + pr) * NX + k0 + LU_NB + c;
                double t1 = g_Wd[a1]; g_Wd[a1] = g_Wd[a2]; g_Wd[a2] = t1;
            }
            __syncthreads();
        }
    }
    if (tid == 0) g_logabsdet += s_logsum;   // panel kernels serialize on stream
}

// U12 = L11^{-1} * A12 : one thread per trailing column, column in registers.
__global__ void lu_rowsolve_kernel(int k0) {
    __shared__ double L[LU_NB][LU_NB + 1];
    int cols2 = NX - k0 - LU_NB;
    for (int i = threadIdx.x; i < LU_NB * LU_NB; i += blockDim.x) {
        int r = i / LU_NB, c = i % LU_NB;
        L[r][c] = g_Wd[(size_t)(k0 + r) * NX + k0 + c];
    }
    __syncthreads();
    int c = blockIdx.x * blockDim.x + threadIdx.x;
    if (c >= cols2) return;
    int gc = k0 + LU_NB + c;
    double a[LU_NB];
    #pragma unroll
    for (int i = 0; i < LU_NB; i++) a[i] = g_Wd[(size_t)(k0 + i) * NX + gc];
    #pragma unroll
    for (int i = 0; i < LU_NB; i++) {
        #pragma unroll
        for (int r = i + 1; r < LU_NB; r++) a[r] -= L[r][i] * a[i];
    }
    #pragma unroll
    for (int i = 0; i < LU_NB; i++) g_Wd[(size_t)(k0 + i) * NX + gc] = a[i];
}

// A22 -= L21 * U12 (fp64, 32x32 tiles, inner dim 32). rows2/cols2 are
// multiples of 32, so no bounds checks needed.
__global__ void lu_trailing_kernel(int k0) {
    __shared__ double Ls[32][33];
    __shared__ double Us[32][33];
    int r0 = blockIdx.y * 32, c0 = blockIdx.x * 32;
    int tid = threadIdx.x;   // 256
    for (int i = tid; i < 32 * 32; i += 256) {
        int rr = i >> 5, cc = i & 31;
        Ls[rr][cc] = g_Wd[(size_t)(k0 + 32 + r0 + rr) * NX + k0 + cc];
        Us[rr][cc] = g_Wd[(size_t)(k0 + rr) * NX + k0 + 32 + c0 + cc];
    }
    __syncthreads();
    int tr = (tid >> 4) * 2;
    int tc = (tid & 15) * 2;
    double a00 = 0, a01 = 0, a10 = 0, a11 = 0;
    #pragma unroll
    for (int k = 0; k < 32; k++) {
        double l0 = Ls[tr][k], l1 = Ls[tr + 1][k];
        double u0 = Us[k][tc], u1 = Us[k][tc + 1];
        a00 += l0 * u0; a01 += l0 * u1; a10 += l1 * u0; a11 += l1 * u1;
    }
    size_t base = (size_t)(k0 + 32 + r0 + tr) * NX + k0 + 32 + c0 + tc;
    g_Wd[base]          -= a00;
    g_Wd[base + 1]      -= a01;
    g_Wd[base + NX]     -= a10;
    g_Wd[base + NX + 1] -= a11;
}

// logDet[i] = Nt * logabsdet  for all samples
__global__ void write_logdet_kernel(float* __restrict__ out_ld) {
    out_ld[threadIdx.x] = (float)((double)NT * g_logabsdet);
}

// ---------------------------------------------------------------------------
// Kernel 3: fused roll + GEMM + roll.
//   out[b, (t-T0)%Nt, y] = sum_u phi[b,t,u] * W[(u+T0)%Nx, y]
// Classic 128x128x8 double-buffered SGEMM, 256 threads, 8x8 per thread.
// ---------------------------------------------------------------------------
#define BM 128
#define BN 128
#define BK 8

__global__ __launch_bounds__(256, 2)
void gemm_roll_kernel(const float* __restrict__ phi,
                      const float* __restrict__ W,
                      float* __restrict__ out) {
    __shared__ __align__(16) float As[2][BK][BM];
    __shared__ __align__(16) float Bs[2][BK][BN];

    const int b  = blockIdx.z;
    const int n0 = blockIdx.x * BN;
    const int m0 = blockIdx.y * BM;
    const int T0 = g_T0[b];

    const float* A = phi + (size_t)b * NT * NX;
    float*       C = out + (size_t)b * NT * NX;

    const int tid  = threadIdx.x;
    const int arow = tid >> 1;           // 0..127
    const int acol = (tid & 1) * 4;      // 0 or 4
    const int br   = tid >> 5;           // 0..7
    const int bc   = (tid & 31) * 4;     // 0..124

    const int mreg = (tid >> 4) * 8;     // row offset in tile
    const int nreg = (tid & 15) * 8;     // col offset in tile

    float acc[8][8];
    #pragma unroll
    for (int i = 0; i < 8; i++)
        #pragma unroll
        for (int j = 0; j < 8; j++) acc[i][j] = 0.0f;

    // prefetch k-tile 0
    {
        float4 av = *(const float4*)(A + (size_t)(m0 + arow) * NX + acol);
        int brr = (br + T0) & (NX - 1);
        float4 bv = *(const float4*)(W + (size_t)brr * NX + n0 + bc);
        As[0][acol + 0][arow] = av.x;
        As[0][acol + 1][arow] = av.y;
        As[0][acol + 2][arow] = av.z;
        As[0][acol + 3][arow] = av.w;
        *(float4*)&Bs[0][br][bc] = bv;
    }
    __syncthreads();

    int buf = 0;
    const int KT = NX / BK;              // 64
    for (int kt = 0; kt < KT; kt++) {
        float4 av2, bv2;
        if (kt < KT - 1) {
            int k0 = (kt + 1) * BK;
            av2 = *(const float4*)(A + (size_t)(m0 + arow) * NX + k0 + acol);
            int brr = (k0 + br + T0) & (NX - 1);
            bv2 = *(const float4*)(W + (size_t)brr * NX + n0 + bc);
        }
        #pragma unroll
        for (int kk = 0; kk < BK; kk++) {
            float4 a0 = *(float4*)&As[buf][kk][mreg];
            float4 a1 = *(float4*)&As[buf][kk][mreg + 4];
            float4 b0 = *(float4*)&Bs[buf][kk][nreg];
            float4 b1 = *(float4*)&Bs[buf][kk][nreg + 4];
            float ar[8] = {a0.x, a0.y, a0.z, a0.w, a1.x, a1.y, a1.z, a1.w};
            float bg[8] = {b0.x, b0.y, b0.z, b0.w, b1.x, b1.y, b1.z, b1.w};
            #pragma unroll
            for (int i = 0; i < 8; i++)
                #pragma unroll
                for (int j = 0; j < 8; j++)
                    acc[i][j] += ar[i] * bg[j];
        }
        if (kt < KT - 1) {
            int nb = buf ^ 1;
            As[nb][acol + 0][arow] = av2.x;
            As[nb][acol + 1][arow] = av2.y;
            As[nb][acol + 2][arow] = av2.z;
            As[nb][acol + 3][arow] = av2.w;
            *(float4*)&Bs[nb][br][bc] = bv2;
            __syncthreads();
            buf = nb;
        }
    }

    // epilogue: row t -> output row (t - T0) mod Nt
    #pragma unroll
    for (int i = 0; i < 8; i++) {
        int t = m0 + mreg + i;
        int orow = (t - T0 + NT) & (NT - 1);
        float* crow = C + (size_t)orow * NX + n0 + nreg;
        *(float4*)(crow)     = make_float4(acc[i][0], acc[i][1], acc[i][2], acc[i][3]);
        *(float4*)(crow + 4) = make_float4(acc[i][4], acc[i][5], acc[i][6], acc[i][7]);
    }
}

// ---------------------------------------------------------------------------
// Launch
// ---------------------------------------------------------------------------
extern "C" void kernel_launch(void* const* d_in, const int* in_sizes, int n_in,
                              void* d_out, int out_size) {
    const float* phi = (const float*)d_in[0];
    const float* W   = (const float*)d_in[1];
    float* out = (float*)d_out;

    // panel kernel needs up to 512*33*8 = 135168 B dynamic smem
    cudaFuncSetAttribute(lu_panel_kernel,
                         cudaFuncAttributeMaxDynamicSharedMemorySize,
                         NX * 33 * (int)sizeof(double));

    // 1) T0 per sample
    argmin_kernel<<<NB, 32>>>(phi);

    // 2) fp64 LU of W for logabsdet
    convert_W_kernel<<<(NX * NX + 255) / 256, 256>>>(W);
    for (int p = 0; p < NX / LU_NB; p++) {
        int k0 = p * LU_NB;
        int R  = NX - k0;
        lu_panel_kernel<<<1, 512, R * 33 * (int)sizeof(double)>>>(k0);
        int cols2 = NX - k0 - LU_NB;
        if (cols2 > 0) {
            lu_rowsolve_kernel<<<(cols2 + 127) / 128, 128>>>(k0);
            dim3 g(cols2 / 32, cols2 / 32);
            lu_trailing_kernel<<<g, 256>>>(k0);
        }
    }
    write_logdet_kernel<<<1, NB>>>(out + (out_size - NB));

    // 3) fused roll->GEMM->roll
    dim3 grid(NX / BN, NT / BM, NB);
    gemm_roll_kernel<<<grid, 256>>>(phi, W, out);
}